// round 13
// baseline (speedup 1.0000x reference)
#include <cuda_runtime.h>
#include <cuda_bf16.h>

#define EPS 1e-6f
#define NB 16
#define NA 10
#define NT 30
#define NP_POLY 16
#define NV 200
#define SEG_PER_POLY (NV - 1)            // 199
#define NSEG (NP_POLY * SEG_PER_POLY)    // 3184 per batch
#define NPTS_WARP 10
#define NPAIR (NPTS_WARP / 2)            // 5
#define WARPS 3
#define THREADS (WARPS * 32)             // 96
#define NBA (NB * NA)                    // 160
#define GRID (NBA * NP_POLY)             // 2560

typedef unsigned long long ull;

#define ADD2(d, a, b)    asm("add.rn.f32x2 %0, %1, %2;"      : "=l"(d) : "l"(a), "l"(b))
#define MUL2(d, a, b)    asm("mul.rn.f32x2 %0, %1, %2;"      : "=l"(d) : "l"(a), "l"(b))
#define FMA2(d, a, b, c) asm("fma.rn.f32x2 %0, %1, %2, %3;"  : "=l"(d) : "l"(a), "l"(b), "l"(c))
#define PACK2(d, lo, hi) asm("mov.b64 %0, {%1, %2};"         : "=l"(d) : "f"(lo), "f"(hi))
#define UNPACK2(lo, hi, s) asm("mov.b64 {%0, %1}, %2;"       : "=f"(lo), "=f"(hi) : "l"(s))

// pre-packed, pre-negated per-segment table: 5 x float4 = 80 B/segment
// q0={-sx,-sx,-sy,-sy} q1={evx,evx,evy,evy} q2={-evx,-evx,-evy,-evy}
// q3={-ey,-ey,rcp_sl,rcp_sl} q4={sx,sx,rcp_esq,rcp_esq}
struct SegP { float4 q0, q1, q2, q3, q4; };
__device__ SegP g_seg[NB * NSEG];

// partial results: [ba][t][poly]  (poly contiguous)
__device__ float g_md[NBA * NT * NP_POLY];
__device__ int   g_ct[NBA * NT * NP_POLY];

__device__ __forceinline__ void pdl_wait() {
    asm volatile("griddepcontrol.wait;" ::: "memory");
}
__device__ __forceinline__ void pdl_trigger() {
    asm volatile("griddepcontrol.launch_dependents;" ::: "memory");
}

__global__ void precompute_kernel(const float* __restrict__ polys) {
    int idx = blockIdx.x * blockDim.x + threadIdx.x;
    if (idx >= NB * NSEG) return;
    int b = idx / NSEG;
    int s = idx - b * NSEG;
    int p = s / SEG_PER_POLY;
    int j = s - p * SEG_PER_POLY;
    const float* v = polys + (((size_t)b * NP_POLY + p) * NV + j) * 2;
    float sx = v[0], sy = v[1], ex = v[2], ey = v[3];
    float evx = ex - sx;                    // same IEEE subs as reference
    float evy = ey - sy;
    float esq = fmaf(evx, evx, evy * evy);
    float rcp_esq = 1.0f / (esq + EPS);     // exact IEEE
    float slope = evy / (evx + EPS);
    float rcp_sl = 1.0f / (slope + EPS);
    SegP sp;
    sp.q0 = make_float4(-sx, -sx, -sy, -sy);
    sp.q1 = make_float4(evx, evx, evy, evy);
    sp.q2 = make_float4(-evx, -evx, -evy, -evy);
    sp.q3 = make_float4(-ey, -ey, rcp_sl, rcp_sl);
    sp.q4 = make_float4(sx, sx, rcp_esq, rcp_esq);
    g_seg[idx] = sp;
}

__global__ __launch_bounds__(THREADS)
void offroad_main_kernel(const float* __restrict__ points) {
    int bx = blockIdx.x;
    int p  = bx & (NP_POLY - 1);
    int ba = bx >> 4;                    // b*NA + a
    int b  = ba / NA;

    int wid = threadIdx.x >> 5;
    int ln  = threadIdx.x & 31;
    int t0  = wid * NPTS_WARP;           // 0,10,20

    ull  px2[NPAIR], py2[NPAIR];
    float qx[NPTS_WARP];                 // scalar px copies (hoisted unpack)
    float md[NPTS_WARP];
    int   ct[NPTS_WARP];

    const float2* pts2 = (const float2*)points;
#pragma unroll
    for (int j = 0; j < NPAIR; j++) {
        float2 p0 = pts2[ba * NT + t0 + 2 * j];
        float2 p1 = pts2[ba * NT + t0 + 2 * j + 1];
        PACK2(px2[j], p0.x, p1.x);
        PACK2(py2[j], p0.y, p1.y);
        qx[2 * j] = p0.x; qx[2 * j + 1] = p1.x;
    }
#pragma unroll
    for (int k = 0; k < NPTS_WARP; k++) { md[k] = 3.4e38f; ct[k] = 0; }

    pdl_wait();   // gate only table reads on precompute completion

    const SegP* tab = g_seg + (b * NSEG + p * SEG_PER_POLY);

#pragma unroll 1
    for (int s = ln; s < SEG_PER_POLY; s += 32) {
        const ull* tp = (const ull*)&tab[s];
        ull nsx2 = __ldg(tp + 0), nsy2  = __ldg(tp + 1);   // q0
        ull evx2 = __ldg(tp + 2), evy2  = __ldg(tp + 3);   // q1
        ull nevx2 = __ldg(tp + 4), nevy2 = __ldg(tp + 5);  // q2
        ull ney2 = __ldg(tp + 6), c12   = __ldg(tp + 7);   // q3
        ull sx2  = __ldg(tp + 8), re2   = __ldg(tp + 9);   // q4
        float rcp_esq, dummy;
        UNPACK2(rcp_esq, dummy, re2);

#pragma unroll
        for (int j = 0; j < NPAIR; j++) {
            ull v1x2, v1y2, tt, dot2, pr2, dx2, dy2, t2, dd2, wy2, ix2;
            ADD2(v1x2, px2[j], nsx2);                 // px - sx
            ADD2(v1y2, py2[j], nsy2);                 // py - sy
            MUL2(tt, v1y2, evy2);
            FMA2(dot2, v1x2, evx2, tt);               // dot
            float d0, d1;
            UNPACK2(d0, d1, dot2);
            float pj0 = __saturatef(d0 * rcp_esq);
            float pj1 = __saturatef(d1 * rcp_esq);
            PACK2(pr2, pj0, pj1);
            FMA2(dx2, nevx2, pr2, v1x2);              // v1x - evx*proj
            FMA2(dy2, nevy2, pr2, v1y2);
            MUL2(t2, dy2, dy2);
            FMA2(dd2, dx2, dx2, t2);                  // d2
            float e0, e1;
            UNPACK2(e0, e1, dd2);
            md[2 * j]     = fminf(md[2 * j],     e0);
            md[2 * j + 1] = fminf(md[2 * j + 1], e1);

            // crossing: cond_y decision-exact via sign bits; ix exact (== R8)
            ADD2(wy2, py2[j], ney2);                  // py - ey
            FMA2(ix2, v1y2, c12, sx2);                // sx + (py-sy)*rcp_sl
            float vy0, vy1, wy0, wy1, ix0, ix1;
            UNPACK2(vy0, vy1, v1y2);
            UNPACK2(wy0, wy1, wy2);
            UNPACK2(ix0, ix1, ix2);
            bool cy0 = ((__float_as_int(vy0) ^ __float_as_int(wy0)) < 0);
            bool cy1 = ((__float_as_int(vy1) ^ __float_as_int(wy1)) < 0);
            ct[2 * j]     += (cy0 & (ix0 > qx[2 * j]))     ? 1 : 0;
            ct[2 * j + 1] += (cy1 & (ix1 > qx[2 * j + 1])) ? 1 : 0;
        }
    }

    // warp reduction
#pragma unroll
    for (int k = 0; k < NPTS_WARP; k++) {
#pragma unroll
        for (int o = 16; o > 0; o >>= 1) {
            md[k] = fminf(md[k], __shfl_xor_sync(0xffffffffu, md[k], o));
            ct[k] += __shfl_xor_sync(0xffffffffu, ct[k], o);
        }
    }

    if (ln == 0) {
#pragma unroll
        for (int k = 0; k < NPTS_WARP; k++) {
            int idx = (ba * NT + t0 + k) * NP_POLY + p;
            g_md[idx] = md[k];
            g_ct[idx] = ct[k];
        }
    }

    __syncthreads();
    pdl_trigger();
}

__global__ __launch_bounds__(32)
void reduce_kernel(float* __restrict__ out) {
    int ba = blockIdx.x;
    int t  = threadIdx.x;

    pdl_wait();

    float loss = 0.0f;
    if (t < NT) {
        float md = 3.4e38f;
        int ct = 0;
        const float4* pm = (const float4*)(g_md + (ba * NT + t) * NP_POLY);
        const int4*   pc = (const int4*)  (g_ct + (ba * NT + t) * NP_POLY);
#pragma unroll
        for (int q = 0; q < NP_POLY / 4; q++) {
            float4 mv = pm[q];
            int4   cv = pc[q];
            md = fminf(md, fminf(fminf(mv.x, mv.y), fminf(mv.z, mv.w)));
            ct += cv.x + cv.y + cv.z + cv.w;
        }
        float d = sqrtf(fmaxf(md, EPS));
        if (ct & 1) d = -d;
        loss = fmaxf(d + 0.5f, 0.0f);
    }
#pragma unroll
    for (int o = 16; o > 0; o >>= 1)
        loss += __shfl_xor_sync(0xffffffffu, loss, o);
    if (t == 0) out[ba] = loss;
}

extern "C" void kernel_launch(void* const* d_in, const int* in_sizes, int n_in,
                              void* d_out, int out_size) {
    const float* points = (const float*)d_in[0];  // (16,10,30,2)
    const float* polys  = (const float*)d_in[1];  // (16,16,200,2)
    float* out = (float*)d_out;                   // (16,10)

    int total = NB * NSEG;
    precompute_kernel<<<(total + 255) / 256, 256>>>(polys);

    cudaLaunchAttribute attr[1];
    attr[0].id = cudaLaunchAttributeProgrammaticStreamSerialization;
    attr[0].val.programmaticStreamSerializationAllowed = 1;

    cudaLaunchConfig_t cfg_main = {};
    cfg_main.gridDim  = dim3(GRID, 1, 1);
    cfg_main.blockDim = dim3(THREADS, 1, 1);
    cfg_main.attrs = attr;
    cfg_main.numAttrs = 1;
    cudaLaunchKernelEx(&cfg_main, offroad_main_kernel, points);

    cudaLaunchConfig_t cfg_red = {};
    cfg_red.gridDim  = dim3(NBA, 1, 1);
    cfg_red.blockDim = dim3(32, 1, 1);
    cfg_red.attrs = attr;
    cfg_red.numAttrs = 1;
    cudaLaunchKernelEx(&cfg_red, reduce_kernel, out);
}

// round 14
// speedup vs baseline: 1.4411x; 1.4411x over previous
#include <cuda_runtime.h>
#include <cuda_bf16.h>

#define EPS 1e-6f
#define NB 16
#define NA 10
#define NT 30
#define NP_POLY 16
#define NV 200
#define SEG_PER_POLY (NV - 1)            // 199
#define NSEG (NP_POLY * SEG_PER_POLY)    // 3184 per batch
#define NPTS_WARP 10
#define NPAIR (NPTS_WARP / 2)            // 5
#define WARPS 3
#define THREADS (WARPS * 32)             // 96
#define NBA (NB * NA)                    // 160
#define GRID (NBA * NP_POLY)             // 2560

typedef unsigned long long ull;

#define ADD2(d, a, b)    asm("add.rn.f32x2 %0, %1, %2;"      : "=l"(d) : "l"(a), "l"(b))
#define MUL2(d, a, b)    asm("mul.rn.f32x2 %0, %1, %2;"      : "=l"(d) : "l"(a), "l"(b))
#define FMA2(d, a, b, c) asm("fma.rn.f32x2 %0, %1, %2, %3;"  : "=l"(d) : "l"(a), "l"(b), "l"(c))
#define PACK2(d, lo, hi) asm("mov.b64 %0, {%1, %2};"         : "=l"(d) : "f"(lo), "f"(hi))
#define UNPACK2(lo, hi, s) asm("mov.b64 {%0, %1}, %2;"       : "=f"(lo), "=f"(hi) : "l"(s))

// per-(batch,segment) tables: two LDG.128 per segment (R12-proven shape)
__device__ float4 g_segA[NB * NSEG];  // {sx, evx, evy, rcp_esq}
__device__ float4 g_segB[NB * NSEG];  // {-sx, -sy, -ey, rcp_sl}

// partial results: [ba][t][poly]  (poly contiguous)
__device__ float g_md[NBA * NT * NP_POLY];
__device__ int   g_ct[NBA * NT * NP_POLY];

__device__ __forceinline__ void pdl_wait() {
    asm volatile("griddepcontrol.wait;" ::: "memory");
}
__device__ __forceinline__ void pdl_trigger() {
    asm volatile("griddepcontrol.launch_dependents;" ::: "memory");
}
__device__ __forceinline__ unsigned warp_redux_min_u32(unsigned v) {
    unsigned r;
    asm("redux.sync.min.u32 %0, %1, 0xffffffff;" : "=r"(r) : "r"(v));
    return r;
}
__device__ __forceinline__ int warp_redux_add_s32(int v) {
    int r;
    asm("redux.sync.add.s32 %0, %1, 0xffffffff;" : "=r"(r) : "r"(v));
    return r;
}

__global__ void precompute_kernel(const float* __restrict__ polys) {
    int idx = blockIdx.x * blockDim.x + threadIdx.x;
    if (idx >= NB * NSEG) return;
    int b = idx / NSEG;
    int s = idx - b * NSEG;
    int p = s / SEG_PER_POLY;
    int j = s - p * SEG_PER_POLY;
    const float* v = polys + (((size_t)b * NP_POLY + p) * NV + j) * 2;
    float sx = v[0], sy = v[1], ex = v[2], ey = v[3];
    float evx = ex - sx;                    // same IEEE subs as reference
    float evy = ey - sy;
    float esq = fmaf(evx, evx, evy * evy);
    float rcp_esq = 1.0f / (esq + EPS);     // exact IEEE
    float slope = evy / (evx + EPS);
    float rcp_sl = 1.0f / (slope + EPS);
    g_segA[idx] = make_float4(sx, evx, evy, rcp_esq);
    g_segB[idx] = make_float4(-sx, -sy, -ey, rcp_sl);
}

__global__ __launch_bounds__(THREADS)
void offroad_main_kernel(const float* __restrict__ points) {
    int bx = blockIdx.x;
    int p  = bx & (NP_POLY - 1);
    int ba = bx >> 4;                    // b*NA + a
    int b  = ba / NA;

    int wid = threadIdx.x >> 5;
    int ln  = threadIdx.x & 31;
    int t0  = wid * NPTS_WARP;           // 0,10,20

    ull  px2[NPAIR], py2[NPAIR];
    float qx[NPTS_WARP];
    float md[NPTS_WARP];
    int   ct[NPTS_WARP];

    const float2* pts2 = (const float2*)points;
#pragma unroll
    for (int j = 0; j < NPAIR; j++) {
        float2 p0 = pts2[ba * NT + t0 + 2 * j];
        float2 p1 = pts2[ba * NT + t0 + 2 * j + 1];
        PACK2(px2[j], p0.x, p1.x);
        PACK2(py2[j], p0.y, p1.y);
        qx[2 * j] = p0.x; qx[2 * j + 1] = p1.x;
    }
#pragma unroll
    for (int k = 0; k < NPTS_WARP; k++) { md[k] = 3.4e38f; ct[k] = 0; }

    pdl_wait();   // gate only table reads on precompute completion

    const float4* sA = g_segA + (b * NSEG + p * SEG_PER_POLY);
    const float4* sB = g_segB + (b * NSEG + p * SEG_PER_POLY);

#pragma unroll 1
    for (int s = ln; s < SEG_PER_POLY; s += 32) {
        float4 a = __ldg(&sA[s]);        // {sx, evx, evy, rcp_esq}
        float4 n = __ldg(&sB[s]);        // {-sx, -sy, -ey, rcp_sl}

        // broadcast pairs (negations pre-baked in table; only 2 negs remain)
        ull nsx2, nsy2, evx2, evy2, nevx2, nevy2, ney2, c12, sx2;
        float nevx = -a.y, nevy = -a.z;
        PACK2(nsx2,  n.x, n.x);  PACK2(nsy2,  n.y, n.y);
        PACK2(evx2,  a.y, a.y);  PACK2(evy2,  a.z, a.z);
        PACK2(nevx2, nevx, nevx); PACK2(nevy2, nevy, nevy);
        PACK2(ney2,  n.z, n.z);
        PACK2(c12,   n.w, n.w);  PACK2(sx2,  a.x, a.x);

#pragma unroll
        for (int j = 0; j < NPAIR; j++) {
            ull v1x2, v1y2, tt, dot2, pr2, dx2, dy2, t2, dd2, wy2, ix2;
            ADD2(v1x2, px2[j], nsx2);                 // px - sx
            ADD2(v1y2, py2[j], nsy2);                 // py - sy
            MUL2(tt, v1y2, evy2);
            FMA2(dot2, v1x2, evx2, tt);               // dot
            float d0, d1;
            UNPACK2(d0, d1, dot2);
            float pj0 = __saturatef(d0 * a.w);
            float pj1 = __saturatef(d1 * a.w);
            PACK2(pr2, pj0, pj1);
            FMA2(dx2, nevx2, pr2, v1x2);              // v1x - evx*proj
            FMA2(dy2, nevy2, pr2, v1y2);
            MUL2(t2, dy2, dy2);
            FMA2(dd2, dx2, dx2, t2);                  // d2
            float e0, e1;
            UNPACK2(e0, e1, dd2);
            md[2 * j]     = fminf(md[2 * j],     e0);
            md[2 * j + 1] = fminf(md[2 * j + 1], e1);

            // crossing: cond_y via exact sign bits; ix exact (== scalar R8 form)
            ADD2(wy2, py2[j], ney2);                  // py - ey
            FMA2(ix2, v1y2, c12, sx2);                // sx + (py-sy)*rcp_sl
            float vy0, vy1, wy0, wy1, ix0, ix1;
            UNPACK2(vy0, vy1, v1y2);
            UNPACK2(wy0, wy1, wy2);
            UNPACK2(ix0, ix1, ix2);
            bool cy0 = ((__float_as_int(vy0) ^ __float_as_int(wy0)) < 0);
            bool cy1 = ((__float_as_int(vy1) ^ __float_as_int(wy1)) < 0);
            ct[2 * j]     += (cy0 & (ix0 > qx[2 * j]))     ? 1 : 0;
            ct[2 * j + 1] += (cy1 & (ix1 > qx[2 * j + 1])) ? 1 : 0;
        }
    }

    // warp fold: redux (bit-min of nonneg f32 == fmin; add exact) — 5x fewer inst
#pragma unroll
    for (int k = 0; k < NPTS_WARP; k++) {
        unsigned mb = warp_redux_min_u32(__float_as_uint(md[k]));
        int      cc = warp_redux_add_s32(ct[k]);
        if (ln == 0) {
            int idx = (ba * NT + t0 + k) * NP_POLY + p;
            g_md[idx] = __uint_as_float(mb);
            g_ct[idx] = cc;
        }
    }

    __syncthreads();
    pdl_trigger();
}

__global__ __launch_bounds__(32)
void reduce_kernel(float* __restrict__ out) {
    int ba = blockIdx.x;
    int t  = threadIdx.x;

    pdl_wait();

    float loss = 0.0f;
    if (t < NT) {
        float md = 3.4e38f;
        int ct = 0;
        const float4* pm = (const float4*)(g_md + (ba * NT + t) * NP_POLY);
        const int4*   pc = (const int4*)  (g_ct + (ba * NT + t) * NP_POLY);
#pragma unroll
        for (int q = 0; q < NP_POLY / 4; q++) {
            float4 mv = pm[q];
            int4   cv = pc[q];
            md = fminf(md, fminf(fminf(mv.x, mv.y), fminf(mv.z, mv.w)));
            ct += cv.x + cv.y + cv.z + cv.w;
        }
        float d = sqrtf(fmaxf(md, EPS));
        if (ct & 1) d = -d;
        loss = fmaxf(d + 0.5f, 0.0f);
    }
#pragma unroll
    for (int o = 16; o > 0; o >>= 1)
        loss += __shfl_xor_sync(0xffffffffu, loss, o);
    if (t == 0) out[ba] = loss;
}

extern "C" void kernel_launch(void* const* d_in, const int* in_sizes, int n_in,
                              void* d_out, int out_size) {
    const float* points = (const float*)d_in[0];  // (16,10,30,2)
    const float* polys  = (const float*)d_in[1];  // (16,16,200,2)
    float* out = (float*)d_out;                   // (16,10)

    int total = NB * NSEG;
    precompute_kernel<<<(total + 255) / 256, 256>>>(polys);

    cudaLaunchAttribute attr[1];
    attr[0].id = cudaLaunchAttributeProgrammaticStreamSerialization;
    attr[0].val.programmaticStreamSerializationAllowed = 1;

    cudaLaunchConfig_t cfg_main = {};
    cfg_main.gridDim  = dim3(GRID, 1, 1);
    cfg_main.blockDim = dim3(THREADS, 1, 1);
    cfg_main.attrs = attr;
    cfg_main.numAttrs = 1;
    cudaLaunchKernelEx(&cfg_main, offroad_main_kernel, points);

    cudaLaunchConfig_t cfg_red = {};
    cfg_red.gridDim  = dim3(NBA, 1, 1);
    cfg_red.blockDim = dim3(32, 1, 1);
    cfg_red.attrs = attr;
    cfg_red.numAttrs = 1;
    cudaLaunchKernelEx(&cfg_red, reduce_kernel, out);
}